// round 12
// baseline (speedup 1.0000x reference)
#include <cuda_runtime.h>
#include <cuda_fp16.h>
#include <cstdint>

#define MAXN 50000
#define MAXE 800000
#define NHEADS 4
#define FDIM 128
#define NEG_SLOPE 0.2f
#define GAT_EPS 1e-16f

// ---------------- scratch (static device globals; no allocation) ----------------
__device__ __half g_h[(size_t)MAXN * FDIM];           // 12.8 MB: h = x @ W^T (fp16)
__device__ float g_asrc[MAXN * NHEADS];               // per-node src logits
__device__ float g_adst[MAXN * NHEADS];               // per-node dst logits
__device__ int   g_deg[MAXN];                         // per-dst degree (zeroed by k_agg)
__device__ int   g_off[MAXN + 1];                     // CSR offsets
__device__ int   g_cur[MAXN];                         // scatter cursors
__device__ unsigned long long g_scanstate[256];       // lookback: (status<<32)|value
__device__ unsigned long long g_sedge[MAXE];          // packed (eid<<32 | src), dst-sorted
__device__ float g_exs[(size_t)MAXE * NHEADS];        // exp(alpha), dst-sorted order
__device__ int   g_idx64;                             // 1 if edge_index is int64

// ---------------- helpers ----------------
__device__ __forceinline__ unsigned f2tf(float x) {
    unsigned u;
    asm("cvt.rna.tf32.f32 %0, %1;" : "=r"(u) : "f"(x));
    return u;
}
__device__ __forceinline__ float lrelu_exp(float v) {
    float a = v > 0.0f ? v : v * NEG_SLOPE;
    return __expf(a);
}
__device__ __forceinline__ void load_edge(const void* ei, int e, int E, int& src, int& dst) {
    if (g_idx64) {
        const long long* p = (const long long*)ei;
        src = (int)p[e];
        dst = (int)p[(size_t)E + e];
    } else {
        const int* p = (const int*)ei;
        src = p[e];
        dst = p[(size_t)E + e];
    }
}
__device__ __forceinline__ void cp16(float* dst_smem, const float* src, int srcsize) {
    uint32_t sa = (uint32_t)__cvta_generic_to_shared(dst_smem);
    asm volatile("cp.async.cg.shared.global [%0], [%1], 16, %2;"
                 :: "r"(sa), "l"(src), "r"(srcsize));
}

// ---------------- GEMM + logits + dtype detect + edge histogram (fused) ----------------
#define GST 36
#define GEMM_SMEM (4 * 128 * GST * 4)   // 73728 B
__global__ __launch_bounds__(256, 2) void k_gemm_att(const float* __restrict__ x,
                                                     const float* __restrict__ W,
                                                     const float* __restrict__ att_src,
                                                     const float* __restrict__ att_dst,
                                                     const void* __restrict__ ei,
                                                     int n, int E) {
    extern __shared__ float sm[];
    float* xs = sm;                       // [2][128][GST]
    float* ws = sm + 2 * 128 * GST;       // [2][128][GST]

    int tid = threadIdx.x;
    int lane = tid & 31, warp = tid >> 5;
    int gid = lane >> 2, tig = lane & 3;
    int mw = warp & 3, nw = warp >> 2;
    int mbase = mw * 32, nbase = nw * 64;
    int row0 = blockIdx.x * 128;

    float acc[2][8][4];
    #pragma unroll
    for (int mf = 0; mf < 2; mf++)
        #pragma unroll
        for (int nf = 0; nf < 8; nf++)
            #pragma unroll
            for (int r = 0; r < 4; r++) acc[mf][nf][r] = 0.0f;

    auto load_chunk = [&](int c) {
        int buf = c & 1;
        int kk = c * 32;
        #pragma unroll
        for (int it = 0; it < 4; it++) {
            int v = tid + it * 256;        // 0..1023
            int m = v >> 3, q = v & 7;
            int gr = row0 + m;
            const float* xsrc = (gr < n) ? &x[(size_t)gr * FDIM + kk + q * 4] : x;
            cp16(&xs[(buf * 128 + m) * GST + q * 4], xsrc, (gr < n) ? 16 : 0);
            cp16(&ws[(buf * 128 + m) * GST + q * 4], &W[(size_t)m * FDIM + kk + q * 4], 16);
        }
        asm volatile("cp.async.commit_group;");
    };

    load_chunk(0);

    // ---- overlapped edge histogram (memory pipe, hidden behind tensor work) ----
    {
        const unsigned* eiw = (const unsigned*)ei;
        int is64 = 1;
        #pragma unroll 8
        for (int k = 1; k < 64; k += 2) {
            if (eiw[k] != 0u) { is64 = 0; break; }
        }
        if (blockIdx.x == 0) {
            if (tid == 0) g_idx64 = is64;
            g_scanstate[tid] = 0ULL;       // reset lookback state (pre-scan, in-stream)
        }
        int stride = gridDim.x * 256;
        if (is64) {
            const long long* p = (const long long*)ei + E;
            for (int e = blockIdx.x * 256 + tid; e < E; e += stride)
                atomicAdd(&g_deg[(int)p[e]], 1);
        } else {
            const int* p = (const int*)ei + E;
            for (int e = blockIdx.x * 256 + tid; e < E; e += stride)
                atomicAdd(&g_deg[p[e]], 1);
        }
    }

    for (int c = 0; c < 4; c++) {
        if (c < 3) {
            load_chunk(c + 1);
            asm volatile("cp.async.wait_group 1;");
        } else {
            asm volatile("cp.async.wait_group 0;");
        }
        __syncthreads();

        const float* xb = xs + (c & 1) * 128 * GST;
        const float* wb = ws + (c & 1) * 128 * GST;
        #pragma unroll
        for (int ks = 0; ks < 4; ks++) {
            int k0 = ks * 8;
            unsigned a[2][4];
            #pragma unroll
            for (int mf = 0; mf < 2; mf++) {
                int r = mbase + mf * 16 + gid;
                a[mf][0] = f2tf(xb[r * GST + k0 + tig]);
                a[mf][1] = f2tf(xb[(r + 8) * GST + k0 + tig]);
                a[mf][2] = f2tf(xb[r * GST + k0 + tig + 4]);
                a[mf][3] = f2tf(xb[(r + 8) * GST + k0 + tig + 4]);
            }
            #pragma unroll
            for (int nf = 0; nf < 8; nf++) {
                int cc = nbase + nf * 8 + gid;
                unsigned b0 = f2tf(wb[cc * GST + k0 + tig]);
                unsigned b1 = f2tf(wb[cc * GST + k0 + tig + 4]);
                #pragma unroll
                for (int mf = 0; mf < 2; mf++) {
                    asm volatile(
                        "mma.sync.aligned.m16n8k8.row.col.f32.tf32.tf32.f32 "
                        "{%0,%1,%2,%3}, {%4,%5,%6,%7}, {%8,%9}, {%0,%1,%2,%3};"
                        : "+f"(acc[mf][nf][0]), "+f"(acc[mf][nf][1]),
                          "+f"(acc[mf][nf][2]), "+f"(acc[mf][nf][3])
                        : "r"(a[mf][0]), "r"(a[mf][1]), "r"(a[mf][2]), "r"(a[mf][3]),
                          "r"(b0), "r"(b1));
                }
            }
        }
        __syncthreads();
    }

    // fused attention logits (fp32 accumulators — full precision)
    float ps[2][2][2], pd[2][2][2];
    #pragma unroll
    for (int i = 0; i < 8; i++) { (&ps[0][0][0])[i] = 0.f; (&pd[0][0][0])[i] = 0.f; }

    #pragma unroll
    for (int nf = 0; nf < 8; nf++) {
        int hh = nf >> 2;
        int head = nw * 2 + hh;
        int cl = (nf & 3) * 8 + tig * 2;
        float as0 = att_src[head * 32 + cl], as1 = att_src[head * 32 + cl + 1];
        float ad0 = att_dst[head * 32 + cl], ad1 = att_dst[head * 32 + cl + 1];
        #pragma unroll
        for (int mf = 0; mf < 2; mf++) {
            ps[mf][0][hh] += acc[mf][nf][0] * as0 + acc[mf][nf][1] * as1;
            ps[mf][1][hh] += acc[mf][nf][2] * as0 + acc[mf][nf][3] * as1;
            pd[mf][0][hh] += acc[mf][nf][0] * ad0 + acc[mf][nf][1] * ad1;
            pd[mf][1][hh] += acc[mf][nf][2] * ad0 + acc[mf][nf][3] * ad1;
        }
    }
    #pragma unroll
    for (int i = 0; i < 8; i++) {
        float* pp = &ps[0][0][0];
        float* qq = &pd[0][0][0];
        pp[i] += __shfl_xor_sync(0xffffffffu, pp[i], 1);
        pp[i] += __shfl_xor_sync(0xffffffffu, pp[i], 2);
        qq[i] += __shfl_xor_sync(0xffffffffu, qq[i], 1);
        qq[i] += __shfl_xor_sync(0xffffffffu, qq[i], 2);
    }
    if (tig == 0) {
        #pragma unroll
        for (int mf = 0; mf < 2; mf++)
            #pragma unroll
            for (int rh = 0; rh < 2; rh++) {
                int r = row0 + mbase + mf * 16 + rh * 8 + gid;
                if (r < n) {
                    #pragma unroll
                    for (int hh = 0; hh < 2; hh++) {
                        g_asrc[r * NHEADS + nw * 2 + hh] = ps[mf][rh][hh];
                        g_adst[r * NHEADS + nw * 2 + hh] = pd[mf][rh][hh];
                    }
                }
            }
    }
    // store h as fp16
    #pragma unroll
    for (int mf = 0; mf < 2; mf++) {
        int r = row0 + mbase + mf * 16 + gid;
        #pragma unroll
        for (int nf = 0; nf < 8; nf++) {
            int c = nbase + nf * 8 + tig * 2;
            if (r < n)
                *(half2*)&g_h[(size_t)r * FDIM + c] = __floats2half2_rn(acc[mf][nf][0], acc[mf][nf][1]);
            if (r + 8 < n)
                *(half2*)&g_h[(size_t)(r + 8) * FDIM + c] = __floats2half2_rn(acc[mf][nf][2], acc[mf][nf][3]);
        }
    }
}

// ---------------- single-pass decoupled-lookback scan ----------------
__global__ __launch_bounds__(256) void k_scan(int n) {
    __shared__ int sh[256];
    __shared__ int s_excl;
    int b = blockIdx.x, t = threadIdx.x;
    int i = b * 256 + t;
    int v = (i < n) ? g_deg[i] : 0;
    sh[t] = v;
    __syncthreads();
    #pragma unroll
    for (int ofs = 1; ofs < 256; ofs <<= 1) {
        int x = (t >= ofs) ? sh[t - ofs] : 0;
        __syncthreads();
        sh[t] += x;
        __syncthreads();
    }
    if (t == 0) {
        unsigned total = (unsigned)sh[255];
        if (b == 0) {
            unsigned long long w = (2ULL << 32) | total;
            asm volatile("st.volatile.global.u64 [%0], %1;" :: "l"(&g_scanstate[0]), "l"(w) : "memory");
            s_excl = 0;
        } else {
            unsigned long long w = (1ULL << 32) | total;
            asm volatile("st.volatile.global.u64 [%0], %1;" :: "l"(&g_scanstate[b]), "l"(w) : "memory");
            unsigned excl = 0;
            for (int p = b - 1; p >= 0; p--) {
                unsigned long long r;
                do {
                    asm volatile("ld.volatile.global.u64 %0, [%1];" : "=l"(r) : "l"(&g_scanstate[p]) : "memory");
                } while ((r >> 32) == 0ULL);
                excl += (unsigned)r;
                if ((r >> 32) == 2ULL) break;
            }
            unsigned long long w2 = (2ULL << 32) | (excl + total);
            asm volatile("st.volatile.global.u64 [%0], %1;" :: "l"(&g_scanstate[b]), "l"(w2) : "memory");
            s_excl = (int)excl;
        }
    }
    __syncthreads();
    int add = s_excl;
    if (i < n) {
        int incl = sh[t] + add;
        g_off[i + 1] = incl;
        g_cur[i] = incl - v;
    }
    if (i == 0) g_off[0] = 0;
}

__global__ void k_scatter(const void* __restrict__ ei, int E) {
    int e = blockIdx.x * blockDim.x + threadIdx.x;
    if (e >= E) return;
    int src, dst;
    load_edge(ei, e, E, src, dst);
    int pos = atomicAdd(&g_cur[dst], 1);
    g_sedge[pos] = ((unsigned long long)(unsigned)e << 32) | (unsigned)src;
}

// ---------------- aggregate: warp per dst, pipelined gather, no output atomics ----------------
__global__ __launch_bounds__(256) void k_agg(float* __restrict__ out,
                                             float* __restrict__ apool,
                                             const float* __restrict__ bias,
                                             int n) {
    int dst = blockIdx.x * 8 + (threadIdx.x >> 5);
    int lane = threadIdx.x & 31;
    if (dst >= n) return;
    int off0 = g_off[dst];
    int deg = g_off[dst + 1] - off0;

    float4 adst = *(const float4*)&g_adst[dst * NHEADS];

    // pass A: exp + per-head sums (strided)
    float4 s = make_float4(0.f, 0.f, 0.f, 0.f);
    for (int j = lane; j < deg; j += 32) {
        unsigned long long se = g_sedge[off0 + j];
        int src = (int)(unsigned)se;
        float4 a = *(const float4*)&g_asrc[src * NHEADS];
        float4 ex;
        ex.x = lrelu_exp(a.x + adst.x);
        ex.y = lrelu_exp(a.y + adst.y);
        ex.z = lrelu_exp(a.z + adst.z);
        ex.w = lrelu_exp(a.w + adst.w);
        *(float4*)&g_exs[(size_t)(off0 + j) * NHEADS] = ex;
        s.x += ex.x; s.y += ex.y; s.z += ex.z; s.w += ex.w;
    }
    #pragma unroll
    for (int o = 16; o > 0; o >>= 1) {
        s.x += __shfl_xor_sync(0xffffffffu, s.x, o);
        s.y += __shfl_xor_sync(0xffffffffu, s.y, o);
        s.z += __shfl_xor_sync(0xffffffffu, s.z, o);
        s.w += __shfl_xor_sync(0xffffffffu, s.w, o);
    }
    float4 rs;
    rs.x = 1.0f / (s.x + GAT_EPS);
    rs.y = 1.0f / (s.y + GAT_EPS);
    rs.z = 1.0f / (s.z + GAT_EPS);
    rs.w = 1.0f / (s.w + GAT_EPS);

    // pass A2: apool (strided)
    for (int j = lane; j < deg; j += 32) {
        float4 ex = *(const float4*)&g_exs[(size_t)(off0 + j) * NHEADS];
        int e = (int)(g_sedge[off0 + j] >> 32);
        apool[e] = 0.25f * (ex.x * rs.x + ex.y * rs.y + ex.z * rs.z + ex.w * rs.w);
    }

    // pass B: 4-edge pipelined accumulation (MLP=4 on the h gather)
    int head = lane >> 3;
    float rs_h = (head & 2) ? ((head & 1) ? rs.w : rs.z)
                            : ((head & 1) ? rs.y : rs.x);
    float4 acc = make_float4(0.f, 0.f, 0.f, 0.f);
    const __half* hb = g_h;
    int j = 0;
    for (; j + 4 <= deg; j += 4) {
        size_t q = (size_t)(off0 + j);
        unsigned long long se0 = g_sedge[q];
        unsigned long long se1 = g_sedge[q + 1];
        unsigned long long se2 = g_sedge[q + 2];
        unsigned long long se3 = g_sedge[q + 3];
        float e0 = g_exs[q * NHEADS + head];
        float e1 = g_exs[(q + 1) * NHEADS + head];
        float e2 = g_exs[(q + 2) * NHEADS + head];
        float e3 = g_exs[(q + 3) * NHEADS + head];
        uint2 r0 = *(const uint2*)&hb[(size_t)(unsigned)se0 * FDIM + lane * 4];
        uint2 r1 = *(const uint2*)&hb[(size_t)(unsigned)se1 * FDIM + lane * 4];
        uint2 r2 = *(const uint2*)&hb[(size_t)(unsigned)se2 * FDIM + lane * 4];
        uint2 r3 = *(const uint2*)&hb[(size_t)(unsigned)se3 * FDIM + lane * 4];
        float c0 = e0 * rs_h, c1 = e1 * rs_h, c2 = e2 * rs_h, c3 = e3 * rs_h;
        float2 a01, a23;
        a01 = __half22float2(*(const half2*)&r0.x); a23 = __half22float2(*(const half2*)&r0.y);
        acc.x = fmaf(c0, a01.x, acc.x); acc.y = fmaf(c0, a01.y, acc.y);
        acc.z = fmaf(c0, a23.x, acc.z); acc.w = fmaf(c0, a23.y, acc.w);
        a01 = __half22float2(*(const half2*)&r1.x); a23 = __half22float2(*(const half2*)&r1.y);
        acc.x = fmaf(c1, a01.x, acc.x); acc.y = fmaf(c1, a01.y, acc.y);
        acc.z = fmaf(c1, a23.x, acc.z); acc.w = fmaf(c1, a23.y, acc.w);
        a01 = __half22float2(*(const half2*)&r2.x); a23 = __half22float2(*(const half2*)&r2.y);
        acc.x = fmaf(c2, a01.x, acc.x); acc.y = fmaf(c2, a01.y, acc.y);
        acc.z = fmaf(c2, a23.x, acc.z); acc.w = fmaf(c2, a23.y, acc.w);
        a01 = __half22float2(*(const half2*)&r3.x); a23 = __half22float2(*(const half2*)&r3.y);
        acc.x = fmaf(c3, a01.x, acc.x); acc.y = fmaf(c3, a01.y, acc.y);
        acc.z = fmaf(c3, a23.x, acc.z); acc.w = fmaf(c3, a23.y, acc.w);
    }
    for (; j < deg; j++) {
        size_t q = (size_t)(off0 + j);
        unsigned long long se = g_sedge[q];
        float c = g_exs[q * NHEADS + head] * rs_h;
        uint2 r = *(const uint2*)&hb[(size_t)(unsigned)se * FDIM + lane * 4];
        float2 a01 = __half22float2(*(const half2*)&r.x);
        float2 a23 = __half22float2(*(const half2*)&r.y);
        acc.x = fmaf(c, a01.x, acc.x); acc.y = fmaf(c, a01.y, acc.y);
        acc.z = fmaf(c, a23.x, acc.z); acc.w = fmaf(c, a23.y, acc.w);
    }
    float4 bv = *(const float4*)&bias[lane * 4];
    acc.x += bv.x; acc.y += bv.y; acc.z += bv.z; acc.w += bv.w;
    *(float4*)&out[(size_t)dst * FDIM + lane * 4] = acc;

    // reset degree counter for the next graph replay
    if (lane == 0) g_deg[dst] = 0;
}

extern "C" void kernel_launch(void* const* d_in, const int* in_sizes, int n_in,
                              void* d_out, int out_size) {
    const float* x       = (const float*)d_in[0];
    const void*  ei      = d_in[1];
    const float* W       = (const float*)d_in[2];
    const float* att_src = (const float*)d_in[3];
    const float* att_dst = (const float*)d_in[4];
    const float* bias    = (const float*)d_in[5];

    int n = in_sizes[0] / FDIM;
    int E = in_sizes[1] / 2;

    float* out   = (float*)d_out;
    float* apool = out + (size_t)n * FDIM;

    int nb = (n + 255) / 256;

    static int smem_set = 0;
    if (!smem_set) {
        cudaFuncSetAttribute(k_gemm_att, cudaFuncAttributeMaxDynamicSharedMemorySize, GEMM_SMEM);
        smem_set = 1;
    }

    k_gemm_att<<<(n + 127) / 128, 256, GEMM_SMEM>>>(x, W, att_src, att_dst, ei, n, E);
    k_scan<<<nb, 256>>>(n);
    k_scatter<<<(E + 255) / 256, 256>>>(ei, E);
    k_agg<<<(n + 7) / 8, 256>>>(out, apool, bias, n);
}

// round 13
// speedup vs baseline: 1.0376x; 1.0376x over previous
#include <cuda_runtime.h>
#include <cuda_fp16.h>
#include <cstdint>

#define MAXN 50000
#define MAXE 800000
#define NHEADS 4
#define FDIM 128
#define NEG_SLOPE 0.2f
#define GAT_EPS 1e-16f

// ---------------- scratch (static device globals; no allocation) ----------------
__device__ __half g_h[(size_t)MAXN * FDIM];           // 12.8 MB: h = x @ W^T (fp16)
__device__ float g_asrc[MAXN * NHEADS];               // per-node src logits
__device__ float g_adst[MAXN * NHEADS];               // per-node dst logits
__device__ int   g_deg[MAXN];                         // per-dst degree (zeroed by k_agg)
__device__ int   g_off[MAXN + 1];                     // CSR offsets
__device__ int   g_cur[MAXN];                         // scatter cursors
__device__ unsigned long long g_scanstate[256];       // lookback: (status<<32)|value
__device__ unsigned long long g_sedge[MAXE];          // packed (eid<<32 | src*256), dst-sorted
__device__ float g_exs[(size_t)MAXE * NHEADS];        // exp(alpha), dst-sorted order
__device__ int   g_idx64;                             // 1 if edge_index is int64

// ---------------- helpers ----------------
__device__ __forceinline__ unsigned f2tf(float x) {
    unsigned u;
    asm("cvt.rna.tf32.f32 %0, %1;" : "=r"(u) : "f"(x));
    return u;
}
__device__ __forceinline__ float lrelu_exp(float v) {
    float a = v > 0.0f ? v : v * NEG_SLOPE;
    return __expf(a);
}
__device__ __forceinline__ void load_edge(const void* ei, int e, int E, int& src, int& dst) {
    if (g_idx64) {
        const long long* p = (const long long*)ei;
        src = (int)p[e];
        dst = (int)p[(size_t)E + e];
    } else {
        const int* p = (const int*)ei;
        src = p[e];
        dst = p[(size_t)E + e];
    }
}
__device__ __forceinline__ void cp16(float* dst_smem, const float* src, int srcsize) {
    uint32_t sa = (uint32_t)__cvta_generic_to_shared(dst_smem);
    asm volatile("cp.async.cg.shared.global [%0], [%1], 16, %2;"
                 :: "r"(sa), "l"(src), "r"(srcsize));
}

// ---------------- GEMM + logits + dtype detect + edge histogram (fused) ----------------
#define GST 36
#define GEMM_SMEM (4 * 128 * GST * 4)   // 73728 B
__global__ __launch_bounds__(256, 2) void k_gemm_att(const float* __restrict__ x,
                                                     const float* __restrict__ W,
                                                     const float* __restrict__ att_src,
                                                     const float* __restrict__ att_dst,
                                                     const void* __restrict__ ei,
                                                     int n, int E) {
    extern __shared__ float sm[];
    float* xs = sm;                       // [2][128][GST]
    float* ws = sm + 2 * 128 * GST;       // [2][128][GST]

    int tid = threadIdx.x;
    int lane = tid & 31, warp = tid >> 5;
    int gid = lane >> 2, tig = lane & 3;
    int mw = warp & 3, nw = warp >> 2;
    int mbase = mw * 32, nbase = nw * 64;
    int row0 = blockIdx.x * 128;

    float acc[2][8][4];
    #pragma unroll
    for (int mf = 0; mf < 2; mf++)
        #pragma unroll
        for (int nf = 0; nf < 8; nf++)
            #pragma unroll
            for (int r = 0; r < 4; r++) acc[mf][nf][r] = 0.0f;

    auto load_chunk = [&](int c) {
        int buf = c & 1;
        int kk = c * 32;
        #pragma unroll
        for (int it = 0; it < 4; it++) {
            int v = tid + it * 256;        // 0..1023
            int m = v >> 3, q = v & 7;
            int gr = row0 + m;
            const float* xsrc = (gr < n) ? &x[(size_t)gr * FDIM + kk + q * 4] : x;
            cp16(&xs[(buf * 128 + m) * GST + q * 4], xsrc, (gr < n) ? 16 : 0);
            cp16(&ws[(buf * 128 + m) * GST + q * 4], &W[(size_t)m * FDIM + kk + q * 4], 16);
        }
        asm volatile("cp.async.commit_group;");
    };

    load_chunk(0);

    // ---- overlapped edge histogram (memory pipe, hidden behind tensor work) ----
    {
        const unsigned* eiw = (const unsigned*)ei;
        int is64 = 1;
        #pragma unroll 8
        for (int k = 1; k < 64; k += 2) {
            if (eiw[k] != 0u) { is64 = 0; break; }
        }
        if (blockIdx.x == 0) {
            if (tid == 0) g_idx64 = is64;
            g_scanstate[tid] = 0ULL;       // reset lookback state (pre-scan, in-stream)
        }
        int stride = gridDim.x * 256;
        if (is64) {
            const long long* p = (const long long*)ei + E;
            for (int e = blockIdx.x * 256 + tid; e < E; e += stride)
                atomicAdd(&g_deg[(int)p[e]], 1);
        } else {
            const int* p = (const int*)ei + E;
            for (int e = blockIdx.x * 256 + tid; e < E; e += stride)
                atomicAdd(&g_deg[p[e]], 1);
        }
    }

    for (int c = 0; c < 4; c++) {
        if (c < 3) {
            load_chunk(c + 1);
            asm volatile("cp.async.wait_group 1;");
        } else {
            asm volatile("cp.async.wait_group 0;");
        }
        __syncthreads();

        const float* xb = xs + (c & 1) * 128 * GST;
        const float* wb = ws + (c & 1) * 128 * GST;
        #pragma unroll
        for (int ks = 0; ks < 4; ks++) {
            int k0 = ks * 8;
            unsigned a[2][4];
            #pragma unroll
            for (int mf = 0; mf < 2; mf++) {
                int r = mbase + mf * 16 + gid;
                a[mf][0] = f2tf(xb[r * GST + k0 + tig]);
                a[mf][1] = f2tf(xb[(r + 8) * GST + k0 + tig]);
                a[mf][2] = f2tf(xb[r * GST + k0 + tig + 4]);
                a[mf][3] = f2tf(xb[(r + 8) * GST + k0 + tig + 4]);
            }
            #pragma unroll
            for (int nf = 0; nf < 8; nf++) {
                int cc = nbase + nf * 8 + gid;
                unsigned b0 = f2tf(wb[cc * GST + k0 + tig]);
                unsigned b1 = f2tf(wb[cc * GST + k0 + tig + 4]);
                #pragma unroll
                for (int mf = 0; mf < 2; mf++) {
                    asm volatile(
                        "mma.sync.aligned.m16n8k8.row.col.f32.tf32.tf32.f32 "
                        "{%0,%1,%2,%3}, {%4,%5,%6,%7}, {%8,%9}, {%0,%1,%2,%3};"
                        : "+f"(acc[mf][nf][0]), "+f"(acc[mf][nf][1]),
                          "+f"(acc[mf][nf][2]), "+f"(acc[mf][nf][3])
                        : "r"(a[mf][0]), "r"(a[mf][1]), "r"(a[mf][2]), "r"(a[mf][3]),
                          "r"(b0), "r"(b1));
                }
            }
        }
        __syncthreads();
    }

    // fused attention logits (fp32 accumulators — full precision)
    float ps[2][2][2], pd[2][2][2];
    #pragma unroll
    for (int i = 0; i < 8; i++) { (&ps[0][0][0])[i] = 0.f; (&pd[0][0][0])[i] = 0.f; }

    #pragma unroll
    for (int nf = 0; nf < 8; nf++) {
        int hh = nf >> 2;
        int head = nw * 2 + hh;
        int cl = (nf & 3) * 8 + tig * 2;
        float as0 = att_src[head * 32 + cl], as1 = att_src[head * 32 + cl + 1];
        float ad0 = att_dst[head * 32 + cl], ad1 = att_dst[head * 32 + cl + 1];
        #pragma unroll
        for (int mf = 0; mf < 2; mf++) {
            ps[mf][0][hh] += acc[mf][nf][0] * as0 + acc[mf][nf][1] * as1;
            ps[mf][1][hh] += acc[mf][nf][2] * as0 + acc[mf][nf][3] * as1;
            pd[mf][0][hh] += acc[mf][nf][0] * ad0 + acc[mf][nf][1] * ad1;
            pd[mf][1][hh] += acc[mf][nf][2] * ad0 + acc[mf][nf][3] * ad1;
        }
    }
    #pragma unroll
    for (int i = 0; i < 8; i++) {
        float* pp = &ps[0][0][0];
        float* qq = &pd[0][0][0];
        pp[i] += __shfl_xor_sync(0xffffffffu, pp[i], 1);
        pp[i] += __shfl_xor_sync(0xffffffffu, pp[i], 2);
        qq[i] += __shfl_xor_sync(0xffffffffu, qq[i], 1);
        qq[i] += __shfl_xor_sync(0xffffffffu, qq[i], 2);
    }
    if (tig == 0) {
        #pragma unroll
        for (int mf = 0; mf < 2; mf++)
            #pragma unroll
            for (int rh = 0; rh < 2; rh++) {
                int r = row0 + mbase + mf * 16 + rh * 8 + gid;
                if (r < n) {
                    #pragma unroll
                    for (int hh = 0; hh < 2; hh++) {
                        g_asrc[r * NHEADS + nw * 2 + hh] = ps[mf][rh][hh];
                        g_adst[r * NHEADS + nw * 2 + hh] = pd[mf][rh][hh];
                    }
                }
            }
    }
    // store h as fp16
    #pragma unroll
    for (int mf = 0; mf < 2; mf++) {
        int r = row0 + mbase + mf * 16 + gid;
        #pragma unroll
        for (int nf = 0; nf < 8; nf++) {
            int c = nbase + nf * 8 + tig * 2;
            if (r < n)
                *(half2*)&g_h[(size_t)r * FDIM + c] = __floats2half2_rn(acc[mf][nf][0], acc[mf][nf][1]);
            if (r + 8 < n)
                *(half2*)&g_h[(size_t)(r + 8) * FDIM + c] = __floats2half2_rn(acc[mf][nf][2], acc[mf][nf][3]);
        }
    }
}

// ---------------- single-pass decoupled-lookback scan ----------------
__global__ __launch_bounds__(256) void k_scan(int n) {
    __shared__ int sh[256];
    __shared__ int s_excl;
    int b = blockIdx.x, t = threadIdx.x;
    int i = b * 256 + t;
    int v = (i < n) ? g_deg[i] : 0;
    sh[t] = v;
    __syncthreads();
    #pragma unroll
    for (int ofs = 1; ofs < 256; ofs <<= 1) {
        int x = (t >= ofs) ? sh[t - ofs] : 0;
        __syncthreads();
        sh[t] += x;
        __syncthreads();
    }
    if (t == 0) {
        unsigned total = (unsigned)sh[255];
        if (b == 0) {
            unsigned long long w = (2ULL << 32) | total;
            asm volatile("st.volatile.global.u64 [%0], %1;" :: "l"(&g_scanstate[0]), "l"(w) : "memory");
            s_excl = 0;
        } else {
            unsigned long long w = (1ULL << 32) | total;
            asm volatile("st.volatile.global.u64 [%0], %1;" :: "l"(&g_scanstate[b]), "l"(w) : "memory");
            unsigned excl = 0;
            for (int p = b - 1; p >= 0; p--) {
                unsigned long long r;
                do {
                    asm volatile("ld.volatile.global.u64 %0, [%1];" : "=l"(r) : "l"(&g_scanstate[p]) : "memory");
                } while ((r >> 32) == 0ULL);
                excl += (unsigned)r;
                if ((r >> 32) == 2ULL) break;
            }
            unsigned long long w2 = (2ULL << 32) | (excl + total);
            asm volatile("st.volatile.global.u64 [%0], %1;" :: "l"(&g_scanstate[b]), "l"(w2) : "memory");
            s_excl = (int)excl;
        }
    }
    __syncthreads();
    int add = s_excl;
    if (i < n) {
        int incl = sh[t] + add;
        g_off[i + 1] = incl;
        g_cur[i] = incl - v;
    }
    if (i == 0) g_off[0] = 0;
}

__global__ void k_scatter(const void* __restrict__ ei, int E) {
    int e = blockIdx.x * blockDim.x + threadIdx.x;
    if (e >= E) return;
    int src, dst;
    load_edge(ei, e, E, src, dst);
    int pos = atomicAdd(&g_cur[dst], 1);
    // pack h-row BYTE offset (src * FDIM * 2 = src<<8) in the low word
    g_sedge[pos] = ((unsigned long long)(unsigned)e << 32) | ((unsigned)src << 8);
}

// ---------------- aggregate: warp per dst, 64-thread blocks, reg-cached edges ----------------
__global__ __launch_bounds__(64) void k_agg(float* __restrict__ out,
                                            float* __restrict__ apool,
                                            const float* __restrict__ bias,
                                            int n) {
    int dst = blockIdx.x * 2 + (threadIdx.x >> 5);
    int lane = threadIdx.x & 31;
    if (dst >= n) return;
    int off0 = g_off[dst];
    int deg = g_off[dst + 1] - off0;

    float4 adst = *(const float4*)&g_adst[dst * NHEADS];
    bool fast = (deg <= 64);

    // pass A: exp + per-head sums
    float4 s = make_float4(0.f, 0.f, 0.f, 0.f);
    unsigned long long se0v = 0, se1v = 0;
    float4 ex0v = make_float4(0.f, 0.f, 0.f, 0.f);
    float4 ex1v = ex0v;
    if (fast) {
        if (lane < deg) {
            se0v = g_sedge[off0 + lane];
            const float* ap = (const float*)((const char*)g_asrc + (((unsigned)se0v) >> 4));
            float4 a = *(const float4*)ap;
            ex0v.x = lrelu_exp(a.x + adst.x);
            ex0v.y = lrelu_exp(a.y + adst.y);
            ex0v.z = lrelu_exp(a.z + adst.z);
            ex0v.w = lrelu_exp(a.w + adst.w);
            *(float4*)&g_exs[(size_t)(off0 + lane) * NHEADS] = ex0v;
            s.x += ex0v.x; s.y += ex0v.y; s.z += ex0v.z; s.w += ex0v.w;
        }
        if (lane + 32 < deg) {
            se1v = g_sedge[off0 + lane + 32];
            const float* ap = (const float*)((const char*)g_asrc + (((unsigned)se1v) >> 4));
            float4 a = *(const float4*)ap;
            ex1v.x = lrelu_exp(a.x + adst.x);
            ex1v.y = lrelu_exp(a.y + adst.y);
            ex1v.z = lrelu_exp(a.z + adst.z);
            ex1v.w = lrelu_exp(a.w + adst.w);
            *(float4*)&g_exs[(size_t)(off0 + lane + 32) * NHEADS] = ex1v;
            s.x += ex1v.x; s.y += ex1v.y; s.z += ex1v.z; s.w += ex1v.w;
        }
    } else {
        for (int j = lane; j < deg; j += 32) {
            unsigned long long se = g_sedge[off0 + j];
            const float* ap = (const float*)((const char*)g_asrc + (((unsigned)se) >> 4));
            float4 a = *(const float4*)ap;
            float4 ex;
            ex.x = lrelu_exp(a.x + adst.x);
            ex.y = lrelu_exp(a.y + adst.y);
            ex.z = lrelu_exp(a.z + adst.z);
            ex.w = lrelu_exp(a.w + adst.w);
            *(float4*)&g_exs[(size_t)(off0 + j) * NHEADS] = ex;
            s.x += ex.x; s.y += ex.y; s.z += ex.z; s.w += ex.w;
        }
    }
    #pragma unroll
    for (int o = 16; o > 0; o >>= 1) {
        s.x += __shfl_xor_sync(0xffffffffu, s.x, o);
        s.y += __shfl_xor_sync(0xffffffffu, s.y, o);
        s.z += __shfl_xor_sync(0xffffffffu, s.z, o);
        s.w += __shfl_xor_sync(0xffffffffu, s.w, o);
    }
    float4 rs;
    rs.x = 1.0f / (s.x + GAT_EPS);
    rs.y = 1.0f / (s.y + GAT_EPS);
    rs.z = 1.0f / (s.z + GAT_EPS);
    rs.w = 1.0f / (s.w + GAT_EPS);

    // pass A2: apool (from registers on the fast path)
    if (fast) {
        if (lane < deg)
            apool[(int)(se0v >> 32)] = 0.25f * (ex0v.x * rs.x + ex0v.y * rs.y +
                                                ex0v.z * rs.z + ex0v.w * rs.w);
        if (lane + 32 < deg)
            apool[(int)(se1v >> 32)] = 0.25f * (ex1v.x * rs.x + ex1v.y * rs.y +
                                                ex1v.z * rs.z + ex1v.w * rs.w);
    } else {
        for (int j = lane; j < deg; j += 32) {
            float4 ex = *(const float4*)&g_exs[(size_t)(off0 + j) * NHEADS];
            int e = (int)(g_sedge[off0 + j] >> 32);
            apool[e] = 0.25f * (ex.x * rs.x + ex.y * rs.y + ex.z * rs.z + ex.w * rs.w);
        }
    }

    // pass B
    int head = lane >> 3;
    float rs_h = (head & 2) ? ((head & 1) ? rs.w : rs.z)
                            : ((head & 1) ? rs.y : rs.x);
    float4 acc = make_float4(0.f, 0.f, 0.f, 0.f);
    const char* hbytes = (const char*)g_h;
    const float* exb = g_exs + (size_t)off0 * NHEADS + head;
    unsigned lane8 = lane * 8;

    if (fast) {
        unsigned lo0 = (unsigned)se0v, lo1 = (unsigned)se1v;
        int d0 = deg < 32 ? deg : 32;
        int j = 0;
        for (; j + 4 <= d0; j += 4) {
            unsigned o0 = __shfl_sync(0xffffffffu, lo0, j);
            unsigned o1 = __shfl_sync(0xffffffffu, lo0, j + 1);
            unsigned o2 = __shfl_sync(0xffffffffu, lo0, j + 2);
            unsigned o3 = __shfl_sync(0xffffffffu, lo0, j + 3);
            float e0 = exb[j * 4], e1 = exb[j * 4 + 4], e2 = exb[j * 4 + 8], e3 = exb[j * 4 + 12];
            uint2 r0 = *(const uint2*)(hbytes + o0 + lane8);
            uint2 r1 = *(const uint2*)(hbytes + o1 + lane8);
            uint2 r2 = *(const uint2*)(hbytes + o2 + lane8);
            uint2 r3 = *(const uint2*)(hbytes + o3 + lane8);
            float c0 = e0 * rs_h, c1 = e1 * rs_h, c2 = e2 * rs_h, c3 = e3 * rs_h;
            float2 a01, a23;
            a01 = __half22float2(*(const half2*)&r0.x); a23 = __half22float2(*(const half2*)&r0.y);
            acc.x = fmaf(c0, a01.x, acc.x); acc.y = fmaf(c0, a01.y, acc.y);
            acc.z = fmaf(c0, a23.x, acc.z); acc.w = fmaf(c0, a23.y, acc.w);
            a01 = __half22float2(*(const half2*)&r1.x); a23 = __half22float2(*(const half2*)&r1.y);
            acc.x = fmaf(c1, a01.x, acc.x); acc.y = fmaf(c1, a01.y, acc.y);
            acc.z = fmaf(c1, a23.x, acc.z); acc.w = fmaf(c1, a23.y, acc.w);
            a01 = __half22float2(*(const half2*)&r2.x); a23 = __half22float2(*(const half2*)&r2.y);
            acc.x = fmaf(c2, a01.x, acc.x); acc.y = fmaf(c2, a01.y, acc.y);
            acc.z = fmaf(c2, a23.x, acc.z); acc.w = fmaf(c2, a23.y, acc.w);
            a01 = __half22float2(*(const half2*)&r3.x); a23 = __half22float2(*(const half2*)&r3.y);
            acc.x = fmaf(c3, a01.x, acc.x); acc.y = fmaf(c3, a01.y, acc.y);
            acc.z = fmaf(c3, a23.x, acc.z); acc.w = fmaf(c3, a23.y, acc.w);
        }
        for (; j < d0; j++) {
            unsigned o = __shfl_sync(0xffffffffu, lo0, j);
            float c = exb[j * 4] * rs_h;
            uint2 r = *(const uint2*)(hbytes + o + lane8);
            float2 a01 = __half22float2(*(const half2*)&r.x);
            float2 a23 = __half22float2(*(const half2*)&r.y);
            acc.x = fmaf(c, a01.x, acc.x); acc.y = fmaf(c, a01.y, acc.y);
            acc.z = fmaf(c, a23.x, acc.z); acc.w = fmaf(c, a23.y, acc.w);
        }
        for (j = 32; j + 4 <= deg; j += 4) {
            unsigned o0 = __shfl_sync(0xffffffffu, lo1, j - 32);
            unsigned o1 = __shfl_sync(0xffffffffu, lo1, j - 31);
            unsigned o2 = __shfl_sync(0xffffffffu, lo1, j - 30);
            unsigned o3 = __shfl_sync(0xffffffffu, lo1, j - 29);
            float e0 = exb[j * 4], e1 = exb[j * 4 + 4], e2 = exb[j * 4 + 8], e3 = exb[j * 4 + 12];
            uint2 r0 = *(const uint2*)(hbytes + o0 + lane8);
            uint2 r1 = *(const uint2*)(hbytes + o1 + lane8);
            uint2 r2 = *(const uint2*)(hbytes + o2 + lane8);
            uint2 r3 = *(const uint2*)(hbytes + o3 + lane8);
            float c0 = e0 * rs_h, c1 = e1 * rs_h, c2 = e2 * rs_h, c3 = e3 * rs_h;
            float2 a01, a23;
            a01 = __half22float2(*(const half2*)&r0.x); a23 = __half22float2(*(const half2*)&r0.y);
            acc.x = fmaf(c0, a01.x, acc.x); acc.y = fmaf(c0, a01.y, acc.y);
            acc.z = fmaf(c0, a23.x, acc.z); acc.w = fmaf(c0, a23.y, acc.w);
            a01 = __half22float2(*(const half2*)&r1.x); a23 = __half22float2(*(const half2*)&r1.y);
            acc.x = fmaf(c1, a01.x, acc.x); acc.y = fmaf(c1, a01.y, acc.y);
            acc.z = fmaf(c1, a23.x, acc.z); acc.w = fmaf(c1, a23.y, acc.w);
            a01 = __half22float2(*(const half2*)&r2.x); a23 = __half22float2(*(const half2*)&r2.y);
            acc.x = fmaf(c2, a01.x, acc.x); acc.y = fmaf(c2, a01.y, acc.y);
            acc.z = fmaf(c2, a23.x, acc.z); acc.w = fmaf(c2, a23.y, acc.w);
            a01 = __half22float2(*(const half2*)&r3.x); a23 = __half22float2(*(const half2*)&r3.y);
            acc.x = fmaf(c3, a01.x, acc.x); acc.y = fmaf(c3, a01.y, acc.y);
            acc.z = fmaf(c3, a23.x, acc.z); acc.w = fmaf(c3, a23.y, acc.w);
        }
        for (; j < deg; j++) {
            unsigned o = __shfl_sync(0xffffffffu, lo1, j - 32);
            float c = exb[j * 4] * rs_h;
            uint2 r = *(const uint2*)(hbytes + o + lane8);
            float2 a01 = __half22float2(*(const half2*)&r.x);
            float2 a23 = __half22float2(*(const half2*)&r.y);
            acc.x = fmaf(c, a01.x, acc.x); acc.y = fmaf(c, a01.y, acc.y);
            acc.z = fmaf(c, a23.x, acc.z); acc.w = fmaf(c, a23.y, acc.w);
        }
    } else {
        for (int j = 0; j < deg; j++) {
            unsigned long long se = g_sedge[off0 + j];          // broadcast
            float c = exb[j * 4] * rs_h;
            uint2 r = *(const uint2*)(hbytes + (unsigned)se + lane8);
            float2 a01 = __half22float2(*(const half2*)&r.x);
            float2 a23 = __half22float2(*(const half2*)&r.y);
            acc.x = fmaf(c, a01.x, acc.x); acc.y = fmaf(c, a01.y, acc.y);
            acc.z = fmaf(c, a23.x, acc.z); acc.w = fmaf(c, a23.y, acc.w);
        }
    }
    float4 bv = *(const float4*)&bias[lane * 4];
    acc.x += bv.x; acc.y += bv.y; acc.z += bv.z; acc.w += bv.w;
    *(float4*)&out[(size_t)dst * FDIM + lane * 4] = acc;

    // reset degree counter for the next graph replay
    if (lane == 0) g_deg[dst] = 0;
}

extern "C" void kernel_launch(void* const* d_in, const int* in_sizes, int n_in,
                              void* d_out, int out_size) {
    const float* x       = (const float*)d_in[0];
    const void*  ei      = d_in[1];
    const float* W       = (const float*)d_in[2];
    const float* att_src = (const float*)d_in[3];
    const float* att_dst = (const float*)d_in[4];
    const float* bias    = (const float*)d_in[5];

    int n = in_sizes[0] / FDIM;
    int E = in_sizes[1] / 2;

    float* out   = (float*)d_out;
    float* apool = out + (size_t)n * FDIM;

    int nb = (n + 255) / 256;

    static int smem_set = 0;
    if (!smem_set) {
        cudaFuncSetAttribute(k_gemm_att, cudaFuncAttributeMaxDynamicSharedMemorySize, GEMM_SMEM);
        smem_set = 1;
    }

    k_gemm_att<<<(n + 127) / 128, 256, GEMM_SMEM>>>(x, W, att_src, att_dst, ei, n, E);
    k_scan<<<nb, 256>>>(n);
    k_scatter<<<(E + 255) / 256, 256>>>(ei, E);
    k_agg<<<(n + 1) / 2, 64>>>(out, apool, bias, n);
}

// round 15
// speedup vs baseline: 1.0639x; 1.0254x over previous
#include <cuda_runtime.h>
#include <cuda_fp16.h>
#include <cstdint>

#define MAXN 50000
#define MAXE 800000
#define NHEADS 4
#define FDIM 128
#define NEG_SLOPE 0.2f
#define GAT_EPS 1e-16f

// ---------------- scratch (static device globals; no allocation) ----------------
__device__ __half g_h[(size_t)MAXN * FDIM];           // 12.8 MB: h = x @ W^T (fp16)
__device__ float g_asrc[MAXN * NHEADS];               // per-node src logits
__device__ float g_adst[MAXN * NHEADS];               // per-node dst logits
__device__ int   g_deg[MAXN];                         // per-dst degree (zeroed by k_agg)
__device__ int   g_off[MAXN + 1];                     // CSR offsets
__device__ int   g_cur[MAXN];                         // scatter cursors
__device__ unsigned long long g_scanstate[256];       // lookback: (status<<32)|value
__device__ unsigned long long g_sedge[MAXE];          // packed (eid<<32 | src*256), dst-sorted
__device__ float g_exs[(size_t)MAXE * NHEADS];        // exp(alpha), dst-sorted order
__device__ int   g_idx64;                             // 1 if edge_index is int64

// ---------------- helpers ----------------
__device__ __forceinline__ unsigned f2tf(float x) {
    unsigned u;
    asm("cvt.rna.tf32.f32 %0, %1;" : "=r"(u) : "f"(x));
    return u;
}
__device__ __forceinline__ float lrelu_exp(float v) {
    float a = v > 0.0f ? v : v * NEG_SLOPE;
    return __expf(a);
}
__device__ __forceinline__ void cp16(float* dst_smem, const float* src, int srcsize) {
    uint32_t sa = (uint32_t)__cvta_generic_to_shared(dst_smem);
    asm volatile("cp.async.cg.shared.global [%0], [%1], 16, %2;"
                 :: "r"(sa), "l"(src), "r"(srcsize));
}

// ---------------- GEMM + logits + dtype detect + edge histogram (fused) ----------------
#define GST 36
#define GEMM_SMEM (4 * 128 * GST * 4)   // 73728 B
__global__ __launch_bounds__(256, 2) void k_gemm_att(const float* __restrict__ x,
                                                     const float* __restrict__ W,
                                                     const float* __restrict__ att_src,
                                                     const float* __restrict__ att_dst,
                                                     const void* __restrict__ ei,
                                                     int n, int E) {
    extern __shared__ float sm[];
    float* xs = sm;                       // [2][128][GST]
    float* ws = sm + 2 * 128 * GST;       // [2][128][GST]

    int tid = threadIdx.x;
    int lane = tid & 31, warp = tid >> 5;
    int gid = lane >> 2, tig = lane & 3;
    int mw = warp & 3, nw = warp >> 2;
    int mbase = mw * 32, nbase = nw * 64;
    int row0 = blockIdx.x * 128;

    float acc[2][8][4];
    #pragma unroll
    for (int mf = 0; mf < 2; mf++)
        #pragma unroll
        for (int nf = 0; nf < 8; nf++)
            #pragma unroll
            for (int r = 0; r < 4; r++) acc[mf][nf][r] = 0.0f;

    auto load_chunk = [&](int c) {
        int buf = c & 1;
        int kk = c * 32;
        #pragma unroll
        for (int it = 0; it < 4; it++) {
            int v = tid + it * 256;        // 0..1023
            int m = v >> 3, q = v & 7;
            int gr = row0 + m;
            const float* xsrc = (gr < n) ? &x[(size_t)gr * FDIM + kk + q * 4] : x;
            cp16(&xs[(buf * 128 + m) * GST + q * 4], xsrc, (gr < n) ? 16 : 0);
            cp16(&ws[(buf * 128 + m) * GST + q * 4], &W[(size_t)m * FDIM + kk + q * 4], 16);
        }
        asm volatile("cp.async.commit_group;");
    };

    load_chunk(0);

    // ---- overlapped edge histogram (memory pipe, hidden behind tensor work) ----
    {
        const unsigned* eiw = (const unsigned*)ei;
        int is64 = 1;
        #pragma unroll 8
        for (int k = 1; k < 64; k += 2) {
            if (eiw[k] != 0u) { is64 = 0; break; }
        }
        if (blockIdx.x == 0) {
            if (tid == 0) g_idx64 = is64;
            g_scanstate[tid] = 0ULL;       // reset lookback state (pre-scan, in-stream)
        }
        int stride = gridDim.x * 256;
        if (is64) {
            const long long* p = (const long long*)ei + E;
            for (int e = blockIdx.x * 256 + tid; e < E; e += stride)
                atomicAdd(&g_deg[(int)p[e]], 1);
        } else {
            const int* p = (const int*)ei + E;
            for (int e = blockIdx.x * 256 + tid; e < E; e += stride)
                atomicAdd(&g_deg[p[e]], 1);
        }
    }

    for (int c = 0; c < 4; c++) {
        if (c < 3) {
            load_chunk(c + 1);
            asm volatile("cp.async.wait_group 1;");
        } else {
            asm volatile("cp.async.wait_group 0;");
        }
        __syncthreads();

        const float* xb = xs + (c & 1) * 128 * GST;
        const float* wb = ws + (c & 1) * 128 * GST;
        #pragma unroll
        for (int ks = 0; ks < 4; ks++) {
            int k0 = ks * 8;
            unsigned a[2][4];
            #pragma unroll
            for (int mf = 0; mf < 2; mf++) {
                int r = mbase + mf * 16 + gid;
                a[mf][0] = f2tf(xb[r * GST + k0 + tig]);
                a[mf][1] = f2tf(xb[(r + 8) * GST + k0 + tig]);
                a[mf][2] = f2tf(xb[r * GST + k0 + tig + 4]);
                a[mf][3] = f2tf(xb[(r + 8) * GST + k0 + tig + 4]);
            }
            #pragma unroll
            for (int nf = 0; nf < 8; nf++) {
                int cc = nbase + nf * 8 + gid;
                unsigned b0 = f2tf(wb[cc * GST + k0 + tig]);
                unsigned b1 = f2tf(wb[cc * GST + k0 + tig + 4]);
                #pragma unroll
                for (int mf = 0; mf < 2; mf++) {
                    asm volatile(
                        "mma.sync.aligned.m16n8k8.row.col.f32.tf32.tf32.f32 "
                        "{%0,%1,%2,%3}, {%4,%5,%6,%7}, {%8,%9}, {%0,%1,%2,%3};"
                        : "+f"(acc[mf][nf][0]), "+f"(acc[mf][nf][1]),
                          "+f"(acc[mf][nf][2]), "+f"(acc[mf][nf][3])
                        : "r"(a[mf][0]), "r"(a[mf][1]), "r"(a[mf][2]), "r"(a[mf][3]),
                          "r"(b0), "r"(b1));
                }
            }
        }
        __syncthreads();
    }

    // fused attention logits (fp32 accumulators — full precision)
    float ps[2][2][2], pd[2][2][2];
    #pragma unroll
    for (int i = 0; i < 8; i++) { (&ps[0][0][0])[i] = 0.f; (&pd[0][0][0])[i] = 0.f; }

    #pragma unroll
    for (int nf = 0; nf < 8; nf++) {
        int hh = nf >> 2;
        int head = nw * 2 + hh;
        int cl = (nf & 3) * 8 + tig * 2;
        float as0 = att_src[head * 32 + cl], as1 = att_src[head * 32 + cl + 1];
        float ad0 = att_dst[head * 32 + cl], ad1 = att_dst[head * 32 + cl + 1];
        #pragma unroll
        for (int mf = 0; mf < 2; mf++) {
            ps[mf][0][hh] += acc[mf][nf][0] * as0 + acc[mf][nf][1] * as1;
            ps[mf][1][hh] += acc[mf][nf][2] * as0 + acc[mf][nf][3] * as1;
            pd[mf][0][hh] += acc[mf][nf][0] * ad0 + acc[mf][nf][1] * ad1;
            pd[mf][1][hh] += acc[mf][nf][2] * ad0 + acc[mf][nf][3] * ad1;
        }
    }
    #pragma unroll
    for (int i = 0; i < 8; i++) {
        float* pp = &ps[0][0][0];
        float* qq = &pd[0][0][0];
        pp[i] += __shfl_xor_sync(0xffffffffu, pp[i], 1);
        pp[i] += __shfl_xor_sync(0xffffffffu, pp[i], 2);
        qq[i] += __shfl_xor_sync(0xffffffffu, qq[i], 1);
        qq[i] += __shfl_xor_sync(0xffffffffu, qq[i], 2);
    }
    if (tig == 0) {
        #pragma unroll
        for (int mf = 0; mf < 2; mf++)
            #pragma unroll
            for (int rh = 0; rh < 2; rh++) {
                int r = row0 + mbase + mf * 16 + rh * 8 + gid;
                if (r < n) {
                    #pragma unroll
                    for (int hh = 0; hh < 2; hh++) {
                        g_asrc[r * NHEADS + nw * 2 + hh] = ps[mf][rh][hh];
                        g_adst[r * NHEADS + nw * 2 + hh] = pd[mf][rh][hh];
                    }
                }
            }
    }
    // store h as fp16
    #pragma unroll
    for (int mf = 0; mf < 2; mf++) {
        int r = row0 + mbase + mf * 16 + gid;
        #pragma unroll
        for (int nf = 0; nf < 8; nf++) {
            int c = nbase + nf * 8 + tig * 2;
            if (r < n)
                *(half2*)&g_h[(size_t)r * FDIM + c] = __floats2half2_rn(acc[mf][nf][0], acc[mf][nf][1]);
            if (r + 8 < n)
                *(half2*)&g_h[(size_t)(r + 8) * FDIM + c] = __floats2half2_rn(acc[mf][nf][2], acc[mf][nf][3]);
        }
    }
}

// ---------------- single-pass decoupled-lookback scan ----------------
__global__ __launch_bounds__(256) void k_scan(int n) {
    __shared__ int sh[256];
    __shared__ int s_excl;
    int b = blockIdx.x, t = threadIdx.x;
    int i = b * 256 + t;
    int v = (i < n) ? g_deg[i] : 0;
    sh[t] = v;
    __syncthreads();
    #pragma unroll
    for (int ofs = 1; ofs < 256; ofs <<= 1) {
        int x = (t >= ofs) ? sh[t - ofs] : 0;
        __syncthreads();
        sh[t] += x;
        __syncthreads();
    }
    if (t == 0) {
        unsigned total = (unsigned)sh[255];
        if (b == 0) {
            unsigned long long w = (2ULL << 32) | total;
            asm volatile("st.volatile.global.u64 [%0], %1;" :: "l"(&g_scanstate[0]), "l"(w) : "memory");
            s_excl = 0;
        } else {
            unsigned long long w = (1ULL << 32) | total;
            asm volatile("st.volatile.global.u64 [%0], %1;" :: "l"(&g_scanstate[b]), "l"(w) : "memory");
            unsigned excl = 0;
            for (int p = b - 1; p >= 0; p--) {
                unsigned long long r;
                do {
                    asm volatile("ld.volatile.global.u64 %0, [%1];" : "=l"(r) : "l"(&g_scanstate[p]) : "memory");
                } while ((r >> 32) == 0ULL);
                excl += (unsigned)r;
                if ((r >> 32) == 2ULL) break;
            }
            unsigned long long w2 = (2ULL << 32) | (excl + total);
            asm volatile("st.volatile.global.u64 [%0], %1;" :: "l"(&g_scanstate[b]), "l"(w2) : "memory");
            s_excl = (int)excl;
        }
    }
    __syncthreads();
    int add = s_excl;
    if (i < n) {
        int incl = sh[t] + add;
        g_off[i + 1] = incl;
        g_cur[i] = incl - v;
    }
    if (i == 0) g_off[0] = 0;
}

// ---------------- scatter: 2 edges per thread, vectorized index loads ----------------
__global__ void k_scatter(const void* __restrict__ ei, int E) {
    int e0 = (blockIdx.x * blockDim.x + threadIdx.x) * 2;
    if (e0 >= E) return;
    int src0, dst0, src1 = 0, dst1 = 0;
    bool has1 = (e0 + 1 < E);
    if (g_idx64) {
        const long long* p = (const long long*)ei;
        if (has1) {
            longlong2 sp = *(const longlong2*)&p[e0];
            longlong2 dp = *(const longlong2*)&p[(size_t)E + e0];
            src0 = (int)sp.x; dst0 = (int)dp.x;
            src1 = (int)sp.y; dst1 = (int)dp.y;
        } else {
            src0 = (int)p[e0]; dst0 = (int)p[(size_t)E + e0];
        }
    } else {
        const int* p = (const int*)ei;
        if (has1) {
            int2 sp = *(const int2*)&p[e0];
            int2 dp = *(const int2*)&p[E + e0];
            src0 = sp.x; dst0 = dp.x; src1 = sp.y; dst1 = dp.y;
        } else {
            src0 = p[e0]; dst0 = p[E + e0];
        }
    }
    int pos0 = atomicAdd(&g_cur[dst0], 1);
    g_sedge[pos0] = ((unsigned long long)(unsigned)e0 << 32) | ((unsigned)src0 << 8);
    if (has1) {
        int pos1 = atomicAdd(&g_cur[dst1], 1);
        g_sedge[pos1] = ((unsigned long long)(unsigned)(e0 + 1) << 32) | ((unsigned)src1 << 8);
    }
}

// ---------------- aggregate: warp per dst, split-warp pass B (2 edges concurrent) ----------------
__global__ __launch_bounds__(64) void k_agg(float* __restrict__ out,
                                            float* __restrict__ apool,
                                            const float* __restrict__ bias,
                                            int n) {
    int dst = blockIdx.x * 2 + (threadIdx.x >> 5);
    int lane = threadIdx.x & 31;
    if (dst >= n) return;
    int off0 = g_off[dst];
    int deg = g_off[dst + 1] - off0;

    float4 adst = *(const float4*)&g_adst[dst * NHEADS];
    bool fast = (deg <= 64);

    // pass A: exp + per-head sums (reg-cached for deg<=64)
    float4 s = make_float4(0.f, 0.f, 0.f, 0.f);
    unsigned long long se0v = 0, se1v = 0;
    float4 ex0v = make_float4(0.f, 0.f, 0.f, 0.f);
    float4 ex1v = ex0v;
    if (fast) {
        if (lane < deg) {
            se0v = g_sedge[off0 + lane];
            const float* ap = (const float*)((const char*)g_asrc + (((unsigned)se0v) >> 4));
            float4 a = *(const float4*)ap;
            ex0v.x = lrelu_exp(a.x + adst.x);
            ex0v.y = lrelu_exp(a.y + adst.y);
            ex0v.z = lrelu_exp(a.z + adst.z);
            ex0v.w = lrelu_exp(a.w + adst.w);
            *(float4*)&g_exs[(size_t)(off0 + lane) * NHEADS] = ex0v;
            s.x += ex0v.x; s.y += ex0v.y; s.z += ex0v.z; s.w += ex0v.w;
        }
        if (lane + 32 < deg) {
            se1v = g_sedge[off0 + lane + 32];
            const float* ap = (const float*)((const char*)g_asrc + (((unsigned)se1v) >> 4));
            float4 a = *(const float4*)ap;
            ex1v.x = lrelu_exp(a.x + adst.x);
            ex1v.y = lrelu_exp(a.y + adst.y);
            ex1v.z = lrelu_exp(a.z + adst.z);
            ex1v.w = lrelu_exp(a.w + adst.w);
            *(float4*)&g_exs[(size_t)(off0 + lane + 32) * NHEADS] = ex1v;
            s.x += ex1v.x; s.y += ex1v.y; s.z += ex1v.z; s.w += ex1v.w;
        }
    } else {
        for (int j = lane; j < deg; j += 32) {
            unsigned long long se = g_sedge[off0 + j];
            const float* ap = (const float*)((const char*)g_asrc + (((unsigned)se) >> 4));
            float4 a = *(const float4*)ap;
            float4 ex;
            ex.x = lrelu_exp(a.x + adst.x);
            ex.y = lrelu_exp(a.y + adst.y);
            ex.z = lrelu_exp(a.z + adst.z);
            ex.w = lrelu_exp(a.w + adst.w);
            *(float4*)&g_exs[(size_t)(off0 + j) * NHEADS] = ex;
            s.x += ex.x; s.y += ex.y; s.z += ex.z; s.w += ex.w;
        }
    }
    #pragma unroll
    for (int o = 16; o > 0; o >>= 1) {
        s.x += __shfl_xor_sync(0xffffffffu, s.x, o);
        s.y += __shfl_xor_sync(0xffffffffu, s.y, o);
        s.z += __shfl_xor_sync(0xffffffffu, s.z, o);
        s.w += __shfl_xor_sync(0xffffffffu, s.w, o);
    }
    float4 rs;
    rs.x = 1.0f / (s.x + GAT_EPS);
    rs.y = 1.0f / (s.y + GAT_EPS);
    rs.z = 1.0f / (s.z + GAT_EPS);
    rs.w = 1.0f / (s.w + GAT_EPS);

    // pass A2: apool (from registers on the fast path)
    if (fast) {
        if (lane < deg)
            apool[(int)(se0v >> 32)] = 0.25f * (ex0v.x * rs.x + ex0v.y * rs.y +
                                                ex0v.z * rs.z + ex0v.w * rs.w);
        if (lane + 32 < deg)
            apool[(int)(se1v >> 32)] = 0.25f * (ex1v.x * rs.x + ex1v.y * rs.y +
                                                ex1v.z * rs.z + ex1v.w * rs.w);
    } else {
        for (int j = lane; j < deg; j += 32) {
            float4 ex = *(const float4*)&g_exs[(size_t)(off0 + j) * NHEADS];
            int e = (int)(g_sedge[off0 + j] >> 32);
            apool[e] = 0.25f * (ex.x * rs.x + ex.y * rs.y + ex.z * rs.z + ex.w * rs.w);
        }
    }

    // pass B: split-warp. Half-warp = one edge, 16 lanes x 16B (uint4) = 128 cols.
    int hl = lane & 15;
    int half = lane >> 4;
    int headB = hl >> 2;                  // cols hl*8.. belong to head hl/4
    float rsb = (headB & 2) ? ((headB & 1) ? rs.w : rs.z)
                            : ((headB & 1) ? rs.y : rs.x);
    const char* hbytes = (const char*)g_h;
    const float* exq = g_exs + (size_t)off0 * NHEADS;
    unsigned lane16 = hl * 16;
    float4 accA = make_float4(0.f, 0.f, 0.f, 0.f);
    float4 accB = accA;

    auto fma8 = [&](float c, uint4 r) {
        float2 t;
        t = __half22float2(*(const half2*)&r.x);
        accA.x = fmaf(c, t.x, accA.x); accA.y = fmaf(c, t.y, accA.y);
        t = __half22float2(*(const half2*)&r.y);
        accA.z = fmaf(c, t.x, accA.z); accA.w = fmaf(c, t.y, accA.w);
        t = __half22float2(*(const half2*)&r.z);
        accB.x = fmaf(c, t.x, accB.x); accB.y = fmaf(c, t.y, accB.y);
        t = __half22float2(*(const half2*)&r.w);
        accB.z = fmaf(c, t.x, accB.z); accB.w = fmaf(c, t.y, accB.w);
    };

    if (fast) {
        unsigned lo0v = (unsigned)se0v, lo1v = (unsigned)se1v;
        int jb = 0;
        for (; jb + 4 <= deg; jb += 4) {
            unsigned lo = (jb < 32) ? lo0v : lo1v;   // warp-uniform (jb multiple of 4)
            int base = jb & 31;
            unsigned o0 = __shfl_sync(0xffffffffu, lo, base + half);
            unsigned o1 = __shfl_sync(0xffffffffu, lo, base + 2 + half);
            float e0 = exq[(jb + half) * NHEADS + headB];
            float e1 = exq[(jb + 2 + half) * NHEADS + headB];
            uint4 r0 = *(const uint4*)(hbytes + o0 + lane16);
            uint4 r1 = *(const uint4*)(hbytes + o1 + lane16);
            fma8(e0 * rsb, r0);
            fma8(e1 * rsb, r1);
        }
        if (jb + 2 <= deg) {
            unsigned lo = (jb < 32) ? lo0v : lo1v;
            unsigned o = __shfl_sync(0xffffffffu, lo, (jb & 31) + half);
            float e = exq[(jb + half) * NHEADS + headB];
            uint4 r = *(const uint4*)(hbytes + o + lane16);
            fma8(e * rsb, r);
            jb += 2;
        }
        if (jb < deg) {
            unsigned lo = (jb < 32) ? lo0v : lo1v;
            unsigned o = __shfl_sync(0xffffffffu, lo, jb & 31);
            if (half == 0) {
                float e = exq[jb * NHEADS + headB];
                uint4 r = *(const uint4*)(hbytes + o + lane16);
                fma8(e * rsb, r);
            }
        }
    } else {
        int jb = 0;
        for (; jb + 2 <= deg; jb += 2) {
            unsigned long long se = g_sedge[off0 + jb + half];   // per-half broadcast
            float e = exq[(jb + half) * NHEADS + headB];
            uint4 r = *(const uint4*)(hbytes + (unsigned)se + lane16);
            fma8(e * rsb, r);
        }
        if (jb < deg && half == 0) {
            unsigned long long se = g_sedge[off0 + jb];
            float e = exq[jb * NHEADS + headB];
            uint4 r = *(const uint4*)(hbytes + (unsigned)se + lane16);
            fma8(e * rsb, r);
        }
    }

    // merge halves
    accA.x += __shfl_xor_sync(0xffffffffu, accA.x, 16);
    accA.y += __shfl_xor_sync(0xffffffffu, accA.y, 16);
    accA.z += __shfl_xor_sync(0xffffffffu, accA.z, 16);
    accA.w += __shfl_xor_sync(0xffffffffu, accA.w, 16);
    accB.x += __shfl_xor_sync(0xffffffffu, accB.x, 16);
    accB.y += __shfl_xor_sync(0xffffffffu, accB.y, 16);
    accB.z += __shfl_xor_sync(0xffffffffu, accB.z, 16);
    accB.w += __shfl_xor_sync(0xffffffffu, accB.w, 16);

    if (half == 0) {
        float4 b0 = *(const float4*)&bias[hl * 8];
        float4 b1 = *(const float4*)&bias[hl * 8 + 4];
        accA.x += b0.x; accA.y += b0.y; accA.z += b0.z; accA.w += b0.w;
        accB.x += b1.x; accB.y += b1.y; accB.z += b1.z; accB.w += b1.w;
        *(float4*)&out[(size_t)dst * FDIM + hl * 8] = accA;
        *(float4*)&out[(size_t)dst * FDIM + hl * 8 + 4] = accB;
    }

    // reset degree counter for the next graph replay
    if (lane == 0) g_deg[dst] = 0;
}

extern "C" void kernel_launch(void* const* d_in, const int* in_sizes, int n_in,
                              void* d_out, int out_size) {
    const float* x       = (const float*)d_in[0];
    const void*  ei      = d_in[1];
    const float* W       = (const float*)d_in[2];
    const float* att_src = (const float*)d_in[3];
    const float* att_dst = (const float*)d_in[4];
    const float* bias    = (const float*)d_in[5];

    int n = in_sizes[0] / FDIM;
    int E = in_sizes[1] / 2;

    float* out   = (float*)d_out;
    float* apool = out + (size_t)n * FDIM;

    int nb = (n + 255) / 256;

    static int smem_set = 0;
    if (!smem_set) {
        cudaFuncSetAttribute(k_gemm_att, cudaFuncAttributeMaxDynamicSharedMemorySize, GEMM_SMEM);
        smem_set = 1;
    }

    k_gemm_att<<<(n + 127) / 128, 256, GEMM_SMEM>>>(x, W, att_src, att_dst, ei, n, E);
    k_scan<<<nb, 256>>>(n);
    int ep = (E + 1) / 2;
    k_scatter<<<(ep + 255) / 256, 256>>>(ei, E);
    k_agg<<<(n + 1) / 2, 64>>>(out, apool, bias, n);
}